// round 1
// baseline (speedup 1.0000x reference)
#include <cuda_runtime.h>
#include <cstdint>

// PreEncoder: per input fp32 f, emit 16 fp32 values in {-1,+1} encoding the
// quirky fp16-style bit pattern used by the reference:
//   W[15]   = sign(f + 0.001)          (1 if f+0.001 < 0)
//   W[14:10]= (ilogb(|f|) + 15) & 31   (two's-complement wrap, |f|==0 -> 0)
//   W[9:0]  = top-10 mantissa bits of normalized |f| (truncated)
// NaN -> 0x7E00, +inf -> 0x7C00, -inf -> 0xFC00.
// out[16i+k] = 2*bit(15-k) - 1 ; exact tie (f+0.001f == 0) -> out = 0.0.

__global__ void __launch_bounds__(256) PreEncoder_69157563400693_kernel(
    const float* __restrict__ x, float* __restrict__ out, int n)
{
    int i = blockIdx.x * blockDim.x + threadIdx.x;
    if (i >= n) return;

    float f = x[i];
    uint32_t au = __float_as_uint(f) & 0x7FFFFFFFu;

    uint32_t W;
    bool normal = (au < 0x7F800000u);
    float s_val = -1.0f;  // (s-0.5)*2 for the sign slot (handles the 0.5 tie)

    if (!normal) {
        if (au > 0x7F800000u) {
            W = 0x7E00u;                                   // NaN pattern
        } else {
            W = (__float_as_uint(f) >> 31) ? 0xFC00u : 0x7C00u;  // +/- inf
        }
    } else {
        float fp = f + 0.001f;
        uint32_t s = (fp < 0.0f) ? 1u : 0u;
        s_val = (fp < 0.0f) ? 1.0f : ((fp == 0.0f) ? 0.0f : -1.0f);

        int e_dec;
        uint32_t T;
        if (au == 0u) {
            e_dec = 0;          // log2(0) clamped to -15 -> e_dec = 0
            T = 0u;
        } else {
            int be = (int)(au >> 23);
            if (be != 0) {
                // normalized: true exponent = be - 127
                e_dec = be - 112;               // (be-127)+15
                T = (au >> 13) & 0x3FFu;        // top 10 mantissa bits
            } else {
                // subnormal (essentially never hit for this dataset)
                int lz = __clz(au);             // >= 9
                e_dec = (31 - lz) - 134;        // (p - 149) + 15, p = MSB index
                T = ((au << lz) << 1) >> 22;    // next 10 bits after leading 1
            }
        }
        W = (s << 15) | (((uint32_t)e_dec & 31u) << 10) | T;
    }

    float v[16];
#pragma unroll
    for (int k = 0; k < 16; k++) {
        uint32_t bit = (W >> (15 - k)) & 1u;
        // bit=1 -> +1.0f (0x3F800000), bit=0 -> -1.0f (0xBF800000)
        v[k] = __uint_as_float(0xBF800000u ^ (bit << 31));
    }
    if (normal) v[0] = s_val;   // exact-tie case can be 0.0

    float4* o = reinterpret_cast<float4*>(out) + (size_t)i * 4;
    o[0] = make_float4(v[0],  v[1],  v[2],  v[3]);
    o[1] = make_float4(v[4],  v[5],  v[6],  v[7]);
    o[2] = make_float4(v[8],  v[9],  v[10], v[11]);
    o[3] = make_float4(v[12], v[13], v[14], v[15]);
}

extern "C" void kernel_launch(void* const* d_in, const int* in_sizes, int n_in,
                              void* d_out, int out_size)
{
    const float* x = (const float*)d_in[0];
    float* out = (float*)d_out;
    int n = in_sizes[0];                 // 2,097,152 elements; out_size = 16n
    int threads = 256;
    int blocks = (n + threads - 1) / threads;
    PreEncoder_69157563400693_kernel<<<blocks, threads>>>(x, out, n);
}

// round 2
// speedup vs baseline: 1.3281x; 1.3281x over previous
#include <cuda_runtime.h>
#include <cstdint>

// PreEncoder: per input fp32 f, emit 16 fp32 values in {-1,+1} encoding the
// quirky fp16-style bit pattern of the reference (sign of f+0.001, exp wrap
// mod 32, truncated 10-bit mantissa; NaN->0x7E00, +/-inf->0x7C00/0xFC00;
// exact tie f+0.001==0 -> 0.0 in the sign slot).
//
// R1: stage output tiles in SMEM and emit via cp.async.bulk (TMA bulk store)
// to bypass the L1tex per-thread store path that bound R0 at 72.5%.

constexpr int THREADS = 256;
constexpr int IN_PER_THREAD = 2;
constexpr int TILE_IN = THREADS * IN_PER_THREAD;   // 512 inputs per CTA
// output tile = TILE_IN * 16 floats = 32 KB

__device__ __forceinline__ void encode16(float f, float* __restrict__ v)
{
    uint32_t au = __float_as_uint(f) & 0x7FFFFFFFu;
    uint32_t W;
    bool normal = (au < 0x7F800000u);
    float s_val = -1.0f;

    if (!normal) {
        if (au > 0x7F800000u) {
            W = 0x7E00u;                                          // NaN
        } else {
            W = (__float_as_uint(f) >> 31) ? 0xFC00u : 0x7C00u;   // +/- inf
        }
    } else {
        float fp = f + 0.001f;
        uint32_t s = (fp < 0.0f) ? 1u : 0u;
        s_val = (fp < 0.0f) ? 1.0f : ((fp == 0.0f) ? 0.0f : -1.0f);

        int e_dec;
        uint32_t T;
        if (au == 0u) {
            e_dec = 0;                       // log2(0) clamped to -15
            T = 0u;
        } else {
            int be = (int)(au >> 23);
            if (be != 0) {
                e_dec = be - 112;            // (be-127)+15
                T = (au >> 13) & 0x3FFu;     // top 10 mantissa bits (truncate)
            } else {
                int lz = __clz(au);          // subnormal input
                e_dec = (31 - lz) - 134;
                T = ((au << lz) << 1) >> 22;
            }
        }
        W = (s << 15) | (((uint32_t)e_dec & 31u) << 10) | T;
    }

#pragma unroll
    for (int k = 0; k < 16; k++) {
        uint32_t bit = (W >> (15 - k)) & 1u;
        v[k] = __uint_as_float(0xBF800000u ^ (bit << 31));  // +/-1.0f
    }
    if (normal) v[0] = s_val;   // exact-tie case can be 0.0
}

__global__ void __launch_bounds__(THREADS) PreEncoder_69157563400693_kernel(
    const float* __restrict__ x, float* __restrict__ out, int n)
{
    __shared__ alignas(128) float tile[TILE_IN * 16];

    int base = blockIdx.x * TILE_IN;

#pragma unroll
    for (int r = 0; r < IN_PER_THREAD; r++) {
        int j = (int)threadIdx.x + r * THREADS;   // slot within tile
        int i = base + j;
        float f = (i < n) ? x[i] : 0.0f;

        float v[16];
        encode16(f, v);

        float4* s = reinterpret_cast<float4*>(tile + (size_t)j * 16);
        s[0] = make_float4(v[0],  v[1],  v[2],  v[3]);
        s[1] = make_float4(v[4],  v[5],  v[6],  v[7]);
        s[2] = make_float4(v[8],  v[9],  v[10], v[11]);
        s[3] = make_float4(v[12], v[13], v[14], v[15]);
    }

    __syncthreads();
    asm volatile("fence.proxy.async.shared::cta;" ::: "memory");

    if (threadIdx.x == 0) {
        int valid_in = n - base;
        if (valid_in > TILE_IN) valid_in = TILE_IN;
        if (valid_in > 0) {
            uint32_t bytes = (uint32_t)valid_in * 64u;   // multiple of 16
            uint32_t saddr;
            asm("{ .reg .u64 t; cvta.to.shared.u64 t, %1; cvt.u32.u64 %0, t; }"
                : "=r"(saddr) : "l"(tile));
            float* gdst = out + (size_t)base * 16;
            asm volatile(
                "cp.async.bulk.global.shared::cta.bulk_group [%0], [%1], %2;"
                :: "l"(gdst), "r"(saddr), "r"(bytes) : "memory");
            asm volatile("cp.async.bulk.commit_group;" ::: "memory");
            asm volatile("cp.async.bulk.wait_group.read 0;" ::: "memory");
        }
    }
    // keep all threads (and the CTA's SMEM) alive until the bulk store has
    // finished reading SMEM
    __syncthreads();
}

extern "C" void kernel_launch(void* const* d_in, const int* in_sizes, int n_in,
                              void* d_out, int out_size)
{
    const float* x = (const float*)d_in[0];
    float* out = (float*)d_out;
    int n = in_sizes[0];                         // 2,097,152
    int blocks = (n + TILE_IN - 1) / TILE_IN;    // 4096
    PreEncoder_69157563400693_kernel<<<blocks, THREADS>>>(x, out, n);
}

// round 3
// speedup vs baseline: 1.3401x; 1.0090x over previous
#include <cuda_runtime.h>
#include <cstdint>

// PreEncoder: per input fp32 f, emit 16 fp32 values in {-1,+1} encoding the
// quirky fp16-style bit pattern of the reference (sign of f+0.001, exp wrap
// mod 32, truncated 10-bit mantissa; NaN->0x7E00, +/-inf->0x7C00/0xFC00;
// exact tie f+0.001==0 -> 0.0 in the sign slot).
//
// R2: warp-autonomous tiles. Each warp encodes 32 inputs into its own 2 KB
// SMEM slice and issues its own cp.async.bulk store — no CTA-wide barriers,
// 16 KB SMEM/CTA -> full 64-warp occupancy to hide the TMA drain tails.

constexpr int THREADS = 256;                 // 8 warps
constexpr int WARPS   = THREADS / 32;
constexpr int TILE_IN = THREADS;             // 1 input per thread per CTA
// per-warp slice: 32 inputs * 64 B = 2 KB ; CTA SMEM = 16 KB

__device__ __forceinline__ void encode16(float f, float* __restrict__ v)
{
    uint32_t au = __float_as_uint(f) & 0x7FFFFFFFu;
    uint32_t W;
    bool normal = (au < 0x7F800000u);
    float s_val = -1.0f;

    if (!normal) {
        if (au > 0x7F800000u) {
            W = 0x7E00u;                                          // NaN
        } else {
            W = (__float_as_uint(f) >> 31) ? 0xFC00u : 0x7C00u;   // +/- inf
        }
    } else {
        float fp = f + 0.001f;
        uint32_t s = (fp < 0.0f) ? 1u : 0u;
        s_val = (fp < 0.0f) ? 1.0f : ((fp == 0.0f) ? 0.0f : -1.0f);

        int e_dec;
        uint32_t T;
        if (au == 0u) {
            e_dec = 0;                       // log2(0) clamped to -15
            T = 0u;
        } else {
            int be = (int)(au >> 23);
            if (be != 0) {
                e_dec = be - 112;            // (be-127)+15
                T = (au >> 13) & 0x3FFu;     // top 10 mantissa bits (truncate)
            } else {
                int lz = __clz(au);          // subnormal input
                e_dec = (31 - lz) - 134;
                T = ((au << lz) << 1) >> 22;
            }
        }
        W = (s << 15) | (((uint32_t)e_dec & 31u) << 10) | T;
    }

#pragma unroll
    for (int k = 0; k < 16; k++) {
        uint32_t bit = (W >> (15 - k)) & 1u;
        v[k] = __uint_as_float(0xBF800000u ^ (bit << 31));  // +/-1.0f
    }
    if (normal) v[0] = s_val;   // exact-tie case can be 0.0
}

__global__ void __launch_bounds__(THREADS) PreEncoder_69157563400693_kernel(
    const float* __restrict__ x, float* __restrict__ out, int n)
{
    __shared__ alignas(128) float tile[TILE_IN * 16];   // 16 KB

    const int lane = (int)threadIdx.x & 31;
    const int warp = (int)threadIdx.x >> 5;

    const int wbase = blockIdx.x * TILE_IN + warp * 32;  // warp's first input
    const int i = wbase + lane;
    const int valid = n - wbase;                         // inputs in this warp

    float f = (i < n) ? x[i] : 0.0f;
    float v[16];
    encode16(f, v);

    if (valid >= 32) {
        // full warp: stage in SMEM, emit via warp-private bulk store
        float* slice = tile + (size_t)warp * 32 * 16;
        float4* s = reinterpret_cast<float4*>(slice + (size_t)lane * 16);
        s[0] = make_float4(v[0],  v[1],  v[2],  v[3]);
        s[1] = make_float4(v[4],  v[5],  v[6],  v[7]);
        s[2] = make_float4(v[8],  v[9],  v[10], v[11]);
        s[3] = make_float4(v[12], v[13], v[14], v[15]);

        __syncwarp();
        if (lane == 0) {
            asm volatile("fence.proxy.async.shared::cta;" ::: "memory");
            uint32_t saddr;
            asm("{ .reg .u64 t; cvta.to.shared.u64 t, %1; cvt.u32.u64 %0, t; }"
                : "=r"(saddr) : "l"(slice));
            float* gdst = out + (size_t)wbase * 16;
            asm volatile(
                "cp.async.bulk.global.shared::cta.bulk_group [%0], [%1], %2;"
                :: "l"(gdst), "r"(saddr), "n"(32 * 64) : "memory");
            asm volatile("cp.async.bulk.commit_group;" ::: "memory");
            asm volatile("cp.async.bulk.wait_group.read 0;" ::: "memory");
        }
        __syncwarp();   // warp's SMEM slice stays live until drain completes
    } else if (i < n) {
        // ragged tail (n % 32 != 0): direct global stores
        float4* o = reinterpret_cast<float4*>(out) + (size_t)i * 4;
        o[0] = make_float4(v[0],  v[1],  v[2],  v[3]);
        o[1] = make_float4(v[4],  v[5],  v[6],  v[7]);
        o[2] = make_float4(v[8],  v[9],  v[10], v[11]);
        o[3] = make_float4(v[12], v[13], v[14], v[15]);
    }
}

extern "C" void kernel_launch(void* const* d_in, const int* in_sizes, int n_in,
                              void* d_out, int out_size)
{
    const float* x = (const float*)d_in[0];
    float* out = (float*)d_out;
    int n = in_sizes[0];                         // 2,097,152
    int blocks = (n + TILE_IN - 1) / TILE_IN;    // 8192
    PreEncoder_69157563400693_kernel<<<blocks, THREADS>>>(x, out, n);
}